// round 2
// baseline (speedup 1.0000x reference)
#include <cuda_runtime.h>
#include <cstdint>

#define NG        1024
#define NMAX      8388608
#define CAP       11264          // static smem floats per group in bisect fallback (44KB)
#define ITERS     30
#define FIXSCALE  1048576.0f     // 2^20 fixed point for S0
#define CNT_SHIFT 44

// ---------------- device scratch (no allocations allowed) ----------------
__device__ unsigned long long g_acc[NG];     // packed: (count<<44) | fix(S0)
__device__ float g_alphas[NG];
__device__ float g_T[NG];
__device__ int   g_infeas[NG];
__device__ int   g_any;
__device__ int   g_gstart[NG + 1];
__device__ int   g_cursor[NG];
__device__ float g_rsorted[NMAX];

// ---------------- kernels ----------------
__global__ void k_zero() {
    int t = blockIdx.x * blockDim.x + threadIdx.x;
    if (t < NG) g_acc[t] = 0ull;
    if (t == 0) g_any = 0;
}

__device__ __forceinline__ void hist_one(unsigned long long* acc, float a, float b, int g) {
    float yr = fmaxf(b, 1e-9f);
    float r  = a / yr;
    float s  = fminf(fmaxf(r, 0.9f), 1.1f);
    unsigned long long v = (unsigned long long)(s * FIXSCALE) + (1ull << CNT_SHIFT);
    atomicAdd(&acc[g], v);
}

__global__ void k_hist(const float4* __restrict__ yraw4, const float4* __restrict__ yreal4,
                       const int4* __restrict__ gid4, int n4,
                       const float* __restrict__ yraw, const float* __restrict__ yreal,
                       const int* __restrict__ gid, int n) {
    __shared__ unsigned long long acc[NG];
    for (int i = threadIdx.x; i < NG; i += blockDim.x) acc[i] = 0ull;
    __syncthreads();

    int stride = gridDim.x * blockDim.x;
    for (int i = blockIdx.x * blockDim.x + threadIdx.x; i < n4; i += stride) {
        float4 a = yraw4[i];
        float4 b = yreal4[i];
        int4   g = gid4[i];
        hist_one(acc, a.x, b.x, g.x);
        hist_one(acc, a.y, b.y, g.y);
        hist_one(acc, a.z, b.z, g.z);
        hist_one(acc, a.w, b.w, g.w);
    }
    // tail (N not multiple of 4)
    int t = blockIdx.x * blockDim.x + threadIdx.x;
    int base = n4 * 4;
    if (t < n - base) hist_one(acc, yraw[base + t], yreal[base + t], gid[base + t]);

    __syncthreads();
    for (int i = threadIdx.x; i < NG; i += blockDim.x) {
        unsigned long long v = acc[i];
        if (v) atomicAdd(&g_acc[i], v);
    }
}

__global__ void k_feas() {
    int g = threadIdx.x;   // exactly NG threads
    unsigned long long a = g_acc[g];
    int cnt  = (int)(a >> CNT_SHIFT);
    float S0 = (float)(a & ((1ull << CNT_SHIFT) - 1ull)) * (1.0f / FIXSCALE);
    float fn = (float)cnt;
    float L = 0.95f * fn, U = 1.05f * fn;
    bool infeas = (cnt > 0) && (S0 < L || S0 > U);
    g_infeas[g] = infeas ? 1 : 0;
    g_alphas[g] = 0.0f;
    g_T[g] = (S0 < L) ? L : U;
    if (infeas) atomicExch(&g_any, 1);

    // exclusive scan of counts -> group start offsets (for fallback path)
    __shared__ int s[NG];
    s[g] = cnt;
    __syncthreads();
    for (int d = 1; d < NG; d <<= 1) {
        int v = (g >= d) ? s[g - d] : 0;
        __syncthreads();
        s[g] += v;
        __syncthreads();
    }
    int start = s[g] - cnt;
    g_gstart[g] = start;
    g_cursor[g] = start;
    if (g == NG - 1) g_gstart[NG] = s[g];
}

// Fallback: scatter r values into group-contiguous order (only if some group infeasible)
__global__ void k_scatter(const float* __restrict__ yraw, const float* __restrict__ yreal,
                          const int* __restrict__ gid, int n) {
    if (g_any == 0) return;
    int stride = gridDim.x * blockDim.x;
    for (int i = blockIdx.x * blockDim.x + threadIdx.x; i < n; i += stride) {
        float yr = fmaxf(yreal[i], 1e-9f);
        float r  = yraw[i] / yr;
        int g = gid[i];
        int pos = atomicAdd(&g_cursor[g], 1);
        if (pos < NMAX) g_rsorted[pos] = r;
    }
}

// Fallback: per-group 30-iteration bisection over cached r values (static smem)
__global__ void k_bisect() {
    int g = blockIdx.x;
    if (!g_infeas[g]) return;
    __shared__ float sr[CAP];
    const int nt = 256;
    int tid = threadIdx.x;
    int start = g_gstart[g];
    int n = g_gstart[g + 1] - start;
    int nc = n < CAP ? n : CAP;
    for (int j = tid; j < nc; j += nt) sr[j] = g_rsorted[start + j];
    __syncthreads();

    float rmn = __int_as_float(0x7f800000);   // +inf
    float rmx = __int_as_float(0xff800000);   // -inf
    for (int j = tid; j < n; j += nt) {
        float v = (j < CAP) ? sr[j] : g_rsorted[start + j];
        rmn = fminf(rmn, v);
        rmx = fmaxf(rmx, v);
    }
    for (int o = 16; o; o >>= 1) {
        rmn = fminf(rmn, __shfl_down_sync(0xffffffffu, rmn, o));
        rmx = fmaxf(rmx, __shfl_down_sync(0xffffffffu, rmx, o));
    }
    __shared__ float smn[8], smx[8], wbuf[8], sS;
    int w = tid >> 5, l = tid & 31;
    if (l == 0) { smn[w] = rmn; smx[w] = rmx; }
    __syncthreads();
    if (tid == 0) {
        for (int k = 1; k < 8; k++) { rmn = fminf(rmn, smn[k]); rmx = fmaxf(rmx, smx[k]); }
        smn[0] = rmn; smx[0] = rmx;
    }
    __syncthreads();
    rmn = smn[0]; rmx = smx[0];

    float lo = 0.9f - rmx - 1.0f;
    float hi = 1.1f - rmn + 1.0f;
    float T = g_T[g];
    float mid = lo;
    for (int it = 0; it < ITERS; ++it) {
        mid = 0.5f * (lo + hi);
        float p = 0.0f;
        for (int j = tid; j < n; j += nt) {
            float v = (j < CAP) ? sr[j] : g_rsorted[start + j];
            p += fminf(fmaxf(v + mid, 0.9f), 1.1f);
        }
        for (int o = 16; o; o >>= 1) p += __shfl_down_sync(0xffffffffu, p, o);
        if (l == 0) wbuf[w] = p;
        __syncthreads();
        if (tid == 0) {
            float S = 0.0f;
            for (int k = 0; k < 8; k++) S += wbuf[k];
            sS = S;
        }
        __syncthreads();
        float S = sS;
        if (S < T) lo = mid; else hi = mid;
        __syncthreads();
    }
    if (tid == 0) g_alphas[g] = mid;
}

__device__ __forceinline__ float out_one(float a, float b, int g) {
    float yr = fmaxf(b, 1e-9f);
    float alpha = __ldg(&g_alphas[g]);
    float v = fmaf(alpha, yr, a);              // == a exactly when alpha == 0
    return fminf(fmaxf(v, 0.9f * yr), 1.1f * yr);
}

__global__ void k_out(const float4* __restrict__ yraw4, const float4* __restrict__ yreal4,
                      const int4* __restrict__ gid4, float4* __restrict__ out4, int n4,
                      const float* __restrict__ yraw, const float* __restrict__ yreal,
                      const int* __restrict__ gid, float* __restrict__ out, int n) {
    int stride = gridDim.x * blockDim.x;
    for (int i = blockIdx.x * blockDim.x + threadIdx.x; i < n4; i += stride) {
        float4 a = yraw4[i];
        float4 b = yreal4[i];
        int4   g = gid4[i];
        float4 o;
        o.x = out_one(a.x, b.x, g.x);
        o.y = out_one(a.y, b.y, g.y);
        o.z = out_one(a.z, b.z, g.z);
        o.w = out_one(a.w, b.w, g.w);
        out4[i] = o;
    }
    int t = blockIdx.x * blockDim.x + threadIdx.x;
    int base = n4 * 4;
    if (t < n - base) out[base + t] = out_one(yraw[base + t], yreal[base + t], gid[base + t]);
}

// ---------------- launch ----------------
extern "C" void kernel_launch(void* const* d_in, const int* in_sizes, int n_in,
                              void* d_out, int out_size) {
    const float* yraw  = (const float*)d_in[0];
    const float* yreal = (const float*)d_in[1];
    const int*   gid   = (const int*)d_in[2];
    float* out = (float*)d_out;
    int n  = in_sizes[0];
    int n4 = n >> 2;

    k_zero<<<1, 1024>>>();
    k_hist<<<512, 256>>>((const float4*)yraw, (const float4*)yreal, (const int4*)gid, n4,
                         yraw, yreal, gid, n);
    k_feas<<<1, NG>>>();
    k_scatter<<<512, 256>>>(yraw, yreal, gid, n);
    k_bisect<<<NG, 256>>>();
    k_out<<<2048, 256>>>((const float4*)yraw, (const float4*)yreal, (const int4*)gid,
                         (float4*)d_out, n4, yraw, yreal, gid, out, n);
}